// round 3
// baseline (speedup 1.0000x reference)
#include <cuda_runtime.h>
#include <math.h>

// Problem constants (fixed by reference: DIM=256, N_HEADS=2, 4 tokens/group)
#define CDIM     256
#define HDIM     128
#define MTILE    32            // tokens per CTA (8 groups)
#define NTHREADS 256
#define NCHUNK   128           // GEMM N-tile
#define KCHUNK   64            // GEMM K-tile
#define WT_STRIDE 65           // padded weight-tile row stride (floats)
#define QKV_STRIDE 772         // padded qkv row stride (768 + 4)

// shared memory layout (floats)
#define S_XN_OFF   0
#define S_QKV_OFF  (MTILE * CDIM)                      // 8192
#define S_WT_OFF   (S_QKV_OFF + MTILE * QKV_STRIDE)    // 8192 + 24704 = 32896
#define S_RED_OFF  (S_WT_OFF + NCHUNK * WT_STRIDE)     // + 8320 = 41216
#define SMEM_FLOATS (S_RED_OFF + 256)                  // 41472
#define SMEM_BYTES  (SMEM_FLOATS * 4)                  // 165888 B

// One N-chunk (128 cols) x full K (256) GEMM: acc[4][4] += A(32xK) * W(128xK)^T
// A in smem (row stride strideA), W row-major in global [*, 256].
// Thread map: rt = tid>>5 (4 rows each), ct = tid&31 (cols ct, ct+32, ct+64, ct+96).
__device__ __forceinline__ void gemm_nchunk(
    const float* __restrict__ sA, int strideA,
    const float* __restrict__ gW, int wrow_base,
    float* __restrict__ s_wt,
    float acc[4][4], int rt, int ct)
{
    for (int kc = 0; kc < CDIM / KCHUNK; ++kc) {
        __syncthreads();   // previous users of s_wt are done
        // stage W[wrow_base .. +127][kc*64 .. +63] into s_wt (padded rows)
        for (int idx = threadIdx.x; idx < NCHUNK * 16; idx += NTHREADS) {
            int o = idx >> 4;
            int q = idx & 15;
            float4 w4 = *(const float4*)(gW + (size_t)(wrow_base + o) * CDIM
                                             + kc * KCHUNK + q * 4);
            float* dst = s_wt + o * WT_STRIDE + q * 4;
            dst[0] = w4.x; dst[1] = w4.y; dst[2] = w4.z; dst[3] = w4.w;
        }
        __syncthreads();

        const float* a0 = sA + (rt * 4) * strideA + kc * KCHUNK;
        #pragma unroll 8
        for (int k = 0; k < KCHUNK; ++k) {
            float a0v = a0[k];
            float a1v = a0[strideA + k];
            float a2v = a0[2 * strideA + k];
            float a3v = a0[3 * strideA + k];
            float b0 = s_wt[(ct      ) * WT_STRIDE + k];
            float b1 = s_wt[(ct + 32 ) * WT_STRIDE + k];
            float b2 = s_wt[(ct + 64 ) * WT_STRIDE + k];
            float b3 = s_wt[(ct + 96 ) * WT_STRIDE + k];
            acc[0][0] += a0v * b0; acc[0][1] += a0v * b1; acc[0][2] += a0v * b2; acc[0][3] += a0v * b3;
            acc[1][0] += a1v * b0; acc[1][1] += a1v * b1; acc[1][2] += a1v * b2; acc[1][3] += a1v * b3;
            acc[2][0] += a2v * b0; acc[2][1] += a2v * b1; acc[2][2] += a2v * b2; acc[2][3] += a2v * b3;
            acc[3][0] += a3v * b0; acc[3][1] += a3v * b1; acc[3][2] += a3v * b2; acc[3][3] += a3v * b3;
        }
    }
}

__global__ void __launch_bounds__(NTHREADS)
ga_fused_kernel(const float* __restrict__ x,
                const float* __restrict__ qkv_w,
                const float* __restrict__ qkv_b,
                const float* __restrict__ out_w,
                const float* __restrict__ out_b,
                const float* __restrict__ ln_g,
                const float* __restrict__ ln_b,
                float* __restrict__ out)
{
    extern __shared__ float sm[];
    float* s_xn  = sm + S_XN_OFF;    // 32 x 256 : x -> x_n -> (reused) attention output o
    float* s_qkv = sm + S_QKV_OFF;   // 32 x 772 (768 used)
    float* s_wt  = sm + S_WT_OFF;    // 128 x 65
    float* s_red = sm + S_RED_OFF;   // per-warp softmax scratch

    const int tid  = threadIdx.x;
    const int tok0 = blockIdx.x * MTILE;

    // ---- Stage 1: load x tile (coalesced float4) ----
    {
        const float4* xg = (const float4*)(x + (size_t)tok0 * CDIM);
        float4* sx4 = (float4*)s_xn;
        #pragma unroll
        for (int i = 0; i < (MTILE * CDIM / 4) / NTHREADS; ++i)
            sx4[i * NTHREADS + tid] = xg[i * NTHREADS + tid];
    }
    __syncthreads();

    // ---- Stage 2: LayerNorm (8 threads per token) ----
    {
        const int t = tid >> 3, sub = tid & 7;
        const float4* row = (const float4*)(s_xn + t * CDIM + sub * 32);
        float4 v[8];
        float s = 0.f, s2 = 0.f;
        #pragma unroll
        for (int q = 0; q < 8; ++q) {
            v[q] = row[q];
            s  += v[q].x + v[q].y + v[q].z + v[q].w;
            s2 += v[q].x * v[q].x + v[q].y * v[q].y + v[q].z * v[q].z + v[q].w * v[q].w;
        }
        #pragma unroll
        for (int m = 1; m < 8; m <<= 1) {
            s  += __shfl_xor_sync(0xffffffffu, s,  m);
            s2 += __shfl_xor_sync(0xffffffffu, s2, m);
        }
        const float mean = s * (1.f / 256.f);
        const float var  = s2 * (1.f / 256.f) - mean * mean;
        const float rstd = rsqrtf(var + 1e-5f);
        float4* wrow = (float4*)(s_xn + t * CDIM + sub * 32);
        #pragma unroll
        for (int q = 0; q < 8; ++q) {
            int k = sub * 32 + q * 4;
            float4 g4 = *(const float4*)(ln_g + k);
            float4 b4 = *(const float4*)(ln_b + k);
            float4 o4;
            o4.x = (v[q].x - mean) * rstd * g4.x + b4.x;
            o4.y = (v[q].y - mean) * rstd * g4.y + b4.y;
            o4.z = (v[q].z - mean) * rstd * g4.z + b4.z;
            o4.w = (v[q].w - mean) * rstd * g4.w + b4.w;
            wrow[q] = o4;
        }
    }
    __syncthreads();

    const int rt = tid >> 5;   // warp id, 4 token-rows each
    const int ct = tid & 31;

    // ---- Stage 3: QKV projection (32 x 768) ----
    for (int nc = 0; nc < 6; ++nc) {
        float acc[4][4];
        #pragma unroll
        for (int r = 0; r < 4; ++r)
            #pragma unroll
            for (int j = 0; j < 4; ++j) acc[r][j] = 0.f;

        gemm_nchunk(s_xn, CDIM, qkv_w, nc * NCHUNK, s_wt, acc, rt, ct);

        #pragma unroll
        for (int j = 0; j < 4; ++j) {
            const int col = nc * NCHUNK + ct + 32 * j;
            const float bb = qkv_b[col];
            #pragma unroll
            for (int r = 0; r < 4; ++r)
                s_qkv[(rt * 4 + r) * QKV_STRIDE + col] = acc[r][j] + bb;
        }
    }
    __syncthreads();

    // ---- Stage 4: attention (4x4 per group/head), one warp per (group,head) pair ----
    {
        const int warp = rt, lane = ct;
        const float SCALE = 0.0883883476483184405f;   // 128^-0.5
        #pragma unroll
        for (int pp = 0; pp < 2; ++pp) {
            const int p = warp + pp * 8;              // 0..15
            const int g = p >> 1, h = p & 1;
            const int t0 = g * 4;
            const float* qb = s_qkv + t0 * QKV_STRIDE + h * HDIM;
            const float* kb = qb + 256;
            const float* vb = qb + 512;

            // scores: lane -> (pid = lane>>1 in [0,16), half = lane&1)
            const int pid = lane >> 1;
            const int si = pid >> 2, sj = pid & 3, half = lane & 1;
            const float* qi = qb + si * QKV_STRIDE + half * 64;
            const float* kj = kb + sj * QKV_STRIDE + half * 64;
            float partial = 0.f;
            #pragma unroll 8
            for (int d = 0; d < 64; ++d) partial += qi[d] * kj[d];
            partial += __shfl_xor_sync(0xffffffffu, partial, 1);
            const float sc = partial * SCALE;

            // softmax over sj (lane bits 1,2)
            float mx = sc;
            mx = fmaxf(mx, __shfl_xor_sync(0xffffffffu, mx, 2));
            mx = fmaxf(mx, __shfl_xor_sync(0xffffffffu, mx, 4));
            float e = __expf(sc - mx);
            float ssum = e;
            ssum += __shfl_xor_sync(0xffffffffu, ssum, 2);
            ssum += __shfl_xor_sync(0xffffffffu, ssum, 4);
            const float P = e / ssum;
            if (half == 0) s_red[warp * 16 + pid] = P;
            __syncwarp();

            // O = P @ V : lane handles 4 contiguous dims
            const int d0 = lane * 4;
            float4 vv[4];
            #pragma unroll
            for (int j2 = 0; j2 < 4; ++j2)
                vv[j2] = *(const float4*)(vb + j2 * QKV_STRIDE + d0);
            #pragma unroll
            for (int i2 = 0; i2 < 4; ++i2) {
                float4 o4 = make_float4(0.f, 0.f, 0.f, 0.f);
                #pragma unroll
                for (int j2 = 0; j2 < 4; ++j2) {
                    const float pij = s_red[warp * 16 + i2 * 4 + j2];
                    o4.x += pij * vv[j2].x;
                    o4.y += pij * vv[j2].y;
                    o4.z += pij * vv[j2].z;
                    o4.w += pij * vv[j2].w;
                }
                // overwrite s_xn with attention output o (x_n no longer needed)
                *(float4*)(s_xn + (t0 + i2) * CDIM + h * HDIM + d0) = o4;
            }
            __syncwarp();   // s_red reused next iteration
        }
    }
    __syncthreads();

    // ---- Stage 5: out projection + bias + residual, write global ----
    for (int nc = 0; nc < 2; ++nc) {
        float acc[4][4];
        #pragma unroll
        for (int r = 0; r < 4; ++r)
            #pragma unroll
            for (int j = 0; j < 4; ++j) acc[r][j] = 0.f;

        gemm_nchunk(s_xn, CDIM, out_w, nc * NCHUNK, s_wt, acc, rt, ct);

        #pragma unroll
        for (int j = 0; j < 4; ++j) {
            const int col = nc * NCHUNK + ct + 32 * j;
            const float bb = out_b[col];
            #pragma unroll
            for (int r = 0; r < 4; ++r) {
                const size_t gi = (size_t)(tok0 + rt * 4 + r) * CDIM + col;
                out[gi] = acc[r][j] + bb + __ldg(x + gi);
            }
        }
    }
}

extern "C" void kernel_launch(void* const* d_in, const int* in_sizes, int n_in,
                              void* d_out, int out_size)
{
    const float* x     = (const float*)d_in[0];
    const float* qkv_w = (const float*)d_in[1];
    const float* qkv_b = (const float*)d_in[2];
    const float* out_w = (const float*)d_in[3];
    const float* out_b = (const float*)d_in[4];
    const float* ln_g  = (const float*)d_in[5];
    const float* ln_b  = (const float*)d_in[6];
    float* out = (float*)d_out;

    const int ntok = in_sizes[0] / CDIM;       // 131072
    const int nblk = ntok / MTILE;             // 4096

    cudaFuncSetAttribute(ga_fused_kernel,
                         cudaFuncAttributeMaxDynamicSharedMemorySize, SMEM_BYTES);
    ga_fused_kernel<<<nblk, NTHREADS, SMEM_BYTES>>>(
        x, qkv_w, qkv_b, out_w, out_b, ln_g, ln_b, out);
}

// round 4
// speedup vs baseline: 1.6109x; 1.6109x over previous
#include <cuda_runtime.h>
#include <math.h>

// Problem constants (fixed by reference: DIM=256, N_HEADS=2, 4 tokens/group)
#define CDIM     256
#define HDIM     128
#define MTILE    32            // tokens per CTA (8 groups)
#define NTHREADS 256
#define NCHUNK   128           // GEMM N-tile
#define KCHUNK   64            // GEMM K-tile
#define WT_STRIDE 65           // padded weight-tile row stride (floats)
#define QKV_STRIDE 772         // padded qkv row stride (768 + 4)

// shared memory layout (floats)
#define S_XN_OFF   0
#define S_QKV_OFF  (MTILE * CDIM)                      // 8192
#define S_WT_OFF   (S_QKV_OFF + MTILE * QKV_STRIDE)    // 8192 + 24704 = 32896
#define S_RED_OFF  (S_WT_OFF + NCHUNK * WT_STRIDE)     // + 8320 = 41216
#define SMEM_FLOATS (S_RED_OFF + 256)                  // 41472
#define SMEM_BYTES  (SMEM_FLOATS * 4)                  // 165888 B

// One N-chunk (128 cols) x full K (256) GEMM: acc[4][4] += A(32xK) * W(128xK)^T
// A in smem (row stride strideA), W row-major in global [*, 256].
// Thread map: rt = tid>>5 (4 rows each), ct = tid&31 (cols ct, ct+32, ct+64, ct+96).
__device__ __forceinline__ void gemm_nchunk(
    const float* __restrict__ sA, int strideA,
    const float* __restrict__ gW, int wrow_base,
    float* __restrict__ s_wt,
    float acc[4][4], int rt, int ct)
{
    for (int kc = 0; kc < CDIM / KCHUNK; ++kc) {
        __syncthreads();   // previous users of s_wt are done
        // stage W[wrow_base .. +127][kc*64 .. +63] into s_wt (padded rows)
        for (int idx = threadIdx.x; idx < NCHUNK * 16; idx += NTHREADS) {
            int o = idx >> 4;
            int q = idx & 15;
            float4 w4 = *(const float4*)(gW + (size_t)(wrow_base + o) * CDIM
                                             + kc * KCHUNK + q * 4);
            float* dst = s_wt + o * WT_STRIDE + q * 4;
            dst[0] = w4.x; dst[1] = w4.y; dst[2] = w4.z; dst[3] = w4.w;
        }
        __syncthreads();

        const float* a0 = sA + (rt * 4) * strideA + kc * KCHUNK;
        #pragma unroll 8
        for (int k = 0; k < KCHUNK; ++k) {
            float a0v = a0[k];
            float a1v = a0[strideA + k];
            float a2v = a0[2 * strideA + k];
            float a3v = a0[3 * strideA + k];
            float b0 = s_wt[(ct      ) * WT_STRIDE + k];
            float b1 = s_wt[(ct + 32 ) * WT_STRIDE + k];
            float b2 = s_wt[(ct + 64 ) * WT_STRIDE + k];
            float b3 = s_wt[(ct + 96 ) * WT_STRIDE + k];
            acc[0][0] += a0v * b0; acc[0][1] += a0v * b1; acc[0][2] += a0v * b2; acc[0][3] += a0v * b3;
            acc[1][0] += a1v * b0; acc[1][1] += a1v * b1; acc[1][2] += a1v * b2; acc[1][3] += a1v * b3;
            acc[2][0] += a2v * b0; acc[2][1] += a2v * b1; acc[2][2] += a2v * b2; acc[2][3] += a2v * b3;
            acc[3][0] += a3v * b0; acc[3][1] += a3v * b1; acc[3][2] += a3v * b2; acc[3][3] += a3v * b3;
        }
    }
}

__global__ void __launch_bounds__(NTHREADS)
ga_fused_kernel(const float* __restrict__ x,
                const float* __restrict__ qkv_w,
                const float* __restrict__ qkv_b,
                const float* __restrict__ out_w,
                const float* __restrict__ out_b,
                const float* __restrict__ ln_g,
                const float* __restrict__ ln_b,
                float* __restrict__ out)
{
    extern __shared__ float sm[];
    float* s_xn  = sm + S_XN_OFF;    // 32 x 256 : x -> x_n -> (reused) attention output o
    float* s_qkv = sm + S_QKV_OFF;   // 32 x 772 (768 used)
    float* s_wt  = sm + S_WT_OFF;    // 128 x 65
    float* s_red = sm + S_RED_OFF;   // per-warp softmax scratch

    const int tid  = threadIdx.x;
    const int tok0 = blockIdx.x * MTILE;

    // ---- Stage 1: load x tile (coalesced float4) ----
    {
        const float4* xg = (const float4*)(x + (size_t)tok0 * CDIM);
        float4* sx4 = (float4*)s_xn;
        #pragma unroll
        for (int i = 0; i < (MTILE * CDIM / 4) / NTHREADS; ++i)
            sx4[i * NTHREADS + tid] = xg[i * NTHREADS + tid];
    }
    __syncthreads();

    // ---- Stage 2: LayerNorm (8 threads per token) ----
    {
        const int t = tid >> 3, sub = tid & 7;
        const float4* row = (const float4*)(s_xn + t * CDIM + sub * 32);
        float4 v[8];
        float s = 0.f, s2 = 0.f;
        #pragma unroll
        for (int q = 0; q < 8; ++q) {
            v[q] = row[q];
            s  += v[q].x + v[q].y + v[q].z + v[q].w;
            s2 += v[q].x * v[q].x + v[q].y * v[q].y + v[q].z * v[q].z + v[q].w * v[q].w;
        }
        #pragma unroll
        for (int m = 1; m < 8; m <<= 1) {
            s  += __shfl_xor_sync(0xffffffffu, s,  m);
            s2 += __shfl_xor_sync(0xffffffffu, s2, m);
        }
        const float mean = s * (1.f / 256.f);
        const float var  = s2 * (1.f / 256.f) - mean * mean;
        const float rstd = rsqrtf(var + 1e-5f);
        float4* wrow = (float4*)(s_xn + t * CDIM + sub * 32);
        #pragma unroll
        for (int q = 0; q < 8; ++q) {
            int k = sub * 32 + q * 4;
            float4 g4 = *(const float4*)(ln_g + k);
            float4 b4 = *(const float4*)(ln_b + k);
            float4 o4;
            o4.x = (v[q].x - mean) * rstd * g4.x + b4.x;
            o4.y = (v[q].y - mean) * rstd * g4.y + b4.y;
            o4.z = (v[q].z - mean) * rstd * g4.z + b4.z;
            o4.w = (v[q].w - mean) * rstd * g4.w + b4.w;
            wrow[q] = o4;
        }
    }
    __syncthreads();

    const int rt = tid >> 5;   // warp id, 4 token-rows each
    const int ct = tid & 31;

    // ---- Stage 3: QKV projection (32 x 768) ----
    for (int nc = 0; nc < 6; ++nc) {
        float acc[4][4];
        #pragma unroll
        for (int r = 0; r < 4; ++r)
            #pragma unroll
            for (int j = 0; j < 4; ++j) acc[r][j] = 0.f;

        gemm_nchunk(s_xn, CDIM, qkv_w, nc * NCHUNK, s_wt, acc, rt, ct);

        #pragma unroll
        for (int j = 0; j < 4; ++j) {
            const int col = nc * NCHUNK + ct + 32 * j;
            const float bb = qkv_b[col];
            #pragma unroll
            for (int r = 0; r < 4; ++r)
                s_qkv[(rt * 4 + r) * QKV_STRIDE + col] = acc[r][j] + bb;
        }
    }
    __syncthreads();

    // ---- Stage 4: attention (4x4 per group/head), one warp per (group,head) pair ----
    {
        const int warp = rt, lane = ct;
        const float SCALE = 0.0883883476483184405f;   // 128^-0.5
        #pragma unroll
        for (int pp = 0; pp < 2; ++pp) {
            const int p = warp + pp * 8;              // 0..15
            const int g = p >> 1, h = p & 1;
            const int t0 = g * 4;
            const float* qb = s_qkv + t0 * QKV_STRIDE + h * HDIM;
            const float* kb = qb + 256;
            const float* vb = qb + 512;

            // scores: lane -> (pid = lane>>1 in [0,16), half = lane&1)
            const int pid = lane >> 1;
            const int si = pid >> 2, sj = pid & 3, half = lane & 1;
            const float* qi = qb + si * QKV_STRIDE + half * 64;
            const float* kj = kb + sj * QKV_STRIDE + half * 64;
            float partial = 0.f;
            #pragma unroll 8
            for (int d = 0; d < 64; ++d) partial += qi[d] * kj[d];
            partial += __shfl_xor_sync(0xffffffffu, partial, 1);
            const float sc = partial * SCALE;

            // softmax over sj (lane bits 1,2)
            float mx = sc;
            mx = fmaxf(mx, __shfl_xor_sync(0xffffffffu, mx, 2));
            mx = fmaxf(mx, __shfl_xor_sync(0xffffffffu, mx, 4));
            float e = __expf(sc - mx);
            float ssum = e;
            ssum += __shfl_xor_sync(0xffffffffu, ssum, 2);
            ssum += __shfl_xor_sync(0xffffffffu, ssum, 4);
            const float P = e / ssum;
            if (half == 0) s_red[warp * 16 + pid] = P;
            __syncwarp();

            // O = P @ V : lane handles 4 contiguous dims
            const int d0 = lane * 4;
            float4 vv[4];
            #pragma unroll
            for (int j2 = 0; j2 < 4; ++j2)
                vv[j2] = *(const float4*)(vb + j2 * QKV_STRIDE + d0);
            #pragma unroll
            for (int i2 = 0; i2 < 4; ++i2) {
                float4 o4 = make_float4(0.f, 0.f, 0.f, 0.f);
                #pragma unroll
                for (int j2 = 0; j2 < 4; ++j2) {
                    const float pij = s_red[warp * 16 + i2 * 4 + j2];
                    o4.x += pij * vv[j2].x;
                    o4.y += pij * vv[j2].y;
                    o4.z += pij * vv[j2].z;
                    o4.w += pij * vv[j2].w;
                }
                // overwrite s_xn with attention output o (x_n no longer needed)
                *(float4*)(s_xn + (t0 + i2) * CDIM + h * HDIM + d0) = o4;
            }
            __syncwarp();   // s_red reused next iteration
        }
    }
    __syncthreads();

    // ---- Stage 5: out projection + bias + residual, write global ----
    for (int nc = 0; nc < 2; ++nc) {
        float acc[4][4];
        #pragma unroll
        for (int r = 0; r < 4; ++r)
            #pragma unroll
            for (int j = 0; j < 4; ++j) acc[r][j] = 0.f;

        gemm_nchunk(s_xn, CDIM, out_w, nc * NCHUNK, s_wt, acc, rt, ct);

        #pragma unroll
        for (int j = 0; j < 4; ++j) {
            const int col = nc * NCHUNK + ct + 32 * j;
            const float bb = out_b[col];
            #pragma unroll
            for (int r = 0; r < 4; ++r) {
                const size_t gi = (size_t)(tok0 + rt * 4 + r) * CDIM + col;
                out[gi] = acc[r][j] + bb + __ldg(x + gi);
            }
        }
    }
}

extern "C" void kernel_launch(void* const* d_in, const int* in_sizes, int n_in,
                              void* d_out, int out_size)
{
    const float* x     = (const float*)d_in[0];
    const float* qkv_w = (const float*)d_in[1];
    const float* qkv_b = (const float*)d_in[2];
    const float* out_w = (const float*)d_in[3];
    const float* out_b = (const float*)d_in[4];
    const float* ln_g  = (const float*)d_in[5];
    const float* ln_b  = (const float*)d_in[6];
    float* out = (float*)d_out;

    const int ntok = in_sizes[0] / CDIM;       // 131072
    const int nblk = ntok / MTILE;             // 4096

    cudaFuncSetAttribute(ga_fused_kernel,
                         cudaFuncAttributeMaxDynamicSharedMemorySize, SMEM_BYTES);
    ga_fused_kernel<<<nblk, NTHREADS, SMEM_BYTES>>>(
        x, qkv_w, qkv_b, out_w, out_b, ln_g, ln_b, out);
}

// round 6
// speedup vs baseline: 4.0261x; 2.4992x over previous
#include <cuda_runtime.h>
#include <cuda_bf16.h>
#include <stdint.h>
#include <math.h>

// ---------------------------------------------------------------------------
#define CDIM     256
#define MTILE    128
#define NTHREADS 256
#define NQKV     768
#define TOTTOK   131072
#define SA       264          // padded tile stride in halves (528B rows, 16B aligned)

// shared memory layout (bytes)
#define S_AH   0                       // A_hi: 128 x SA halves = 67584 B
#define S_AL   (128 * SA * 2)          // A_lo: 67584 B
#define S_B    (2 * 128 * SA * 2)      // B tile: 67584 B
#define S_BIAS (3 * 128 * SA * 2)      // 1024 floats
#define S_RED  (S_BIAS + 4096)         // 128 floats softmax scratch
#define SMEM_BYTES (S_RED + 512)       // 207360 B

// ---------------------------------------------------------------------------
// device scratch (static __device__ globals only — no runtime alloc)
__device__ float          g_qkv[(size_t)TOTTOK * NQKV];
__device__ __nv_bfloat16  g_whi[(NQKV + CDIM) * CDIM];
__device__ __nv_bfloat16  g_wlo[(NQKV + CDIM) * CDIM];

// ---------------------------------------------------------------------------
// m16n8k16 bf16 MMA (sm_80+ baseline feature, compiles for compute_103)
#define MMA16816(c, a, b0, b1) \
    asm volatile("mma.sync.aligned.m16n8k16.row.col.f32.bf16.bf16.f32 " \
        "{%0,%1,%2,%3}, {%4,%5,%6,%7}, {%8,%9}, {%0,%1,%2,%3};" \
        : "+f"((c)[0]), "+f"((c)[1]), "+f"((c)[2]), "+f"((c)[3]) \
        : "r"((a)[0]), "r"((a)[1]), "r"((a)[2]), "r"((a)[3]), \
          "r"(b0), "r"(b1))

// split 4 fp32 -> packed bf16 hi/lo words
#define SPLIT4(a0,a1,a2,a3,HI0,HI1,LO0,LO1) do { \
    __nv_bfloat16 _h0=__float2bfloat16(a0), _h1=__float2bfloat16(a1); \
    __nv_bfloat16 _h2=__float2bfloat16(a2), _h3=__float2bfloat16(a3); \
    __nv_bfloat16 _l0=__float2bfloat16((a0)-__bfloat162float(_h0)); \
    __nv_bfloat16 _l1=__float2bfloat16((a1)-__bfloat162float(_h1)); \
    __nv_bfloat16 _l2=__float2bfloat16((a2)-__bfloat162float(_h2)); \
    __nv_bfloat16 _l3=__float2bfloat16((a3)-__bfloat162float(_h3)); \
    HI0 = ((uint32_t)__bfloat16_as_ushort(_h1) << 16) | __bfloat16_as_ushort(_h0); \
    HI1 = ((uint32_t)__bfloat16_as_ushort(_h3) << 16) | __bfloat16_as_ushort(_h2); \
    LO0 = ((uint32_t)__bfloat16_as_ushort(_l1) << 16) | __bfloat16_as_ushort(_l0); \
    LO1 = ((uint32_t)__bfloat16_as_ushort(_l3) << 16) | __bfloat16_as_ushort(_l2); \
} while (0)

// ---------------------------------------------------------------------------
// prep kernel: split weights to bf16 hi/lo. rows 0..767 = qkv_w, 768..1023 = out_w
__global__ void ga_prep_w(const float* __restrict__ qkv_w,
                          const float* __restrict__ out_w) {
    int i = blockIdx.x * blockDim.x + threadIdx.x;     // < 1024*256
    float v = (i < NQKV * CDIM) ? qkv_w[i] : out_w[i - NQKV * CDIM];
    __nv_bfloat16 h = __float2bfloat16(v);
    g_whi[i] = h;
    g_wlo[i] = __float2bfloat16(v - __bfloat162float(h));
}

// ---------------------------------------------------------------------------
// stage a 128-row x 256-col bf16 weight chunk into padded smem tile
__device__ __forceinline__ void load_b(const __nv_bfloat16* __restrict__ w,
                                       int row_base, __nv_bfloat16* Bs,
                                       int t, int nthr) {
    for (int i = t; i < 4096; i += nthr) {
        int r = i >> 5, q = i & 31;
        uint4 v = __ldg((const uint4*)(w + ((size_t)(row_base + r) << 8)) + q);
        *(uint4*)(Bs + r * SA + q * 8) = v;
    }
}

// one K=256 chain: c[4][4][4] += A(64x256 slice) * B(32x256 slice)^T
__device__ __forceinline__ void gemm_accum(
    const __nv_bfloat16* __restrict__ As,
    const __nv_bfloat16* __restrict__ Bs,
    float c[4][4][4], int a_row, int b_row, int ac)
{
    #pragma unroll 2
    for (int k0 = 0; k0 < 256; k0 += 16) {
        uint32_t a[4][4];
        #pragma unroll
        for (int m = 0; m < 4; m++) {
            const __nv_bfloat16* ap = As + (a_row + m * 16) * SA + k0 + ac;
            a[m][0] = *(const uint32_t*)(ap);
            a[m][1] = *(const uint32_t*)(ap + 8 * SA);
            a[m][2] = *(const uint32_t*)(ap + 8);
            a[m][3] = *(const uint32_t*)(ap + 8 * SA + 8);
        }
        #pragma unroll
        for (int j = 0; j < 4; j++) {
            const __nv_bfloat16* bp = Bs + (b_row + j * 8) * SA + k0 + ac;
            uint32_t b0 = *(const uint32_t*)(bp);
            uint32_t b1 = *(const uint32_t*)(bp + 8);
            #pragma unroll
            for (int m = 0; m < 4; m++)
                MMA16816(c[m][j], a[m], b0, b1);
        }
    }
}

// ---------------------------------------------------------------------------
__global__ void __launch_bounds__(NTHREADS, 1)
ga_main(const float* __restrict__ x,
        const float* __restrict__ qkv_b,
        const float* __restrict__ out_b,
        const float* __restrict__ ln_g,
        const float* __restrict__ ln_b,
        float* __restrict__ out)
{
    extern __shared__ char smem[];
    __nv_bfloat16* Ah    = (__nv_bfloat16*)(smem + S_AH);
    __nv_bfloat16* Al    = (__nv_bfloat16*)(smem + S_AL);
    __nv_bfloat16* Bs    = (__nv_bfloat16*)(smem + S_B);
    float*         s_bias= (float*)(smem + S_BIAS);
    float*         s_red = (float*)(smem + S_RED);

    const int tid  = threadIdx.x;
    const int wid  = tid >> 5;
    const int lane = tid & 31;
    const int warp_m = wid & 1;        // 2 x M64
    const int warp_n = wid >> 1;       // 4 x N32
    const int tok0 = blockIdx.x * MTILE;

    const int a_row = warp_m * 64 + (lane >> 2);
    const int b_row = warp_n * 32 + (lane >> 2);
    const int ac    = (lane & 3) * 2;

    for (int i = tid; i < 1024; i += NTHREADS)
        s_bias[i] = (i < NQKV) ? __ldg(qkv_b + i) : __ldg(out_b + i - NQKV);

    // ---- Phase A: warps 0-3 LN + split -> Ah/Al; warps 4-7 preload B chunk 0
    if (tid < 128) {
        const float* xr = x + ((size_t)(tok0 + tid) << 8);
        float s = 0.f, s2 = 0.f;
        #pragma unroll 8
        for (int j = 0; j < 64; j++) {
            float4 v = __ldg((const float4*)xr + j);
            s  += v.x + v.y + v.z + v.w;
            s2 += v.x * v.x + v.y * v.y + v.z * v.z + v.w * v.w;
        }
        const float mean = s * (1.f / 256.f);
        const float rstd = rsqrtf(s2 * (1.f / 256.f) - mean * mean + 1e-5f);
        __nv_bfloat16* ah = Ah + tid * SA;
        __nv_bfloat16* al = Al + tid * SA;
        #pragma unroll 4
        for (int j = 0; j < 64; j++) {
            const int k = j * 4;
            float4 v  = __ldg((const float4*)xr + j);
            float4 g4 = __ldg((const float4*)(ln_g + k));
            float4 b4 = __ldg((const float4*)(ln_b + k));
            float a0 = (v.x - mean) * rstd * g4.x + b4.x;
            float a1 = (v.y - mean) * rstd * g4.y + b4.y;
            float a2 = (v.z - mean) * rstd * g4.z + b4.z;
            float a3 = (v.w - mean) * rstd * g4.w + b4.w;
            uint32_t h0, h1, l0, l1;
            SPLIT4(a0, a1, a2, a3, h0, h1, l0, l1);
            *(uint2*)(ah + k) = make_uint2(h0, h1);
            *(uint2*)(al + k) = make_uint2(l0, l1);
        }
    } else {
        load_b(g_whi, 0, Bs, tid - 128, 128);
    }
    __syncthreads();

    // ---- Phase B: QKV projection, 6 N-chunks of 128
    for (int nc = 0; nc < 6; nc++) {
        float c[4][4][4];
        #pragma unroll
        for (int m = 0; m < 4; m++)
            #pragma unroll
            for (int j = 0; j < 4; j++)
                #pragma unroll
                for (int q = 0; q < 4; q++) c[m][j][q] = 0.f;

        gemm_accum(Ah, Bs, c, a_row, b_row, ac);   // Ah * Whi
        gemm_accum(Al, Bs, c, a_row, b_row, ac);   // Al * Whi
        __syncthreads();
        load_b(g_wlo, nc * 128, Bs, tid, NTHREADS);
        __syncthreads();
        gemm_accum(Ah, Bs, c, a_row, b_row, ac);   // Ah * Wlo
        __syncthreads();
        if (nc < 5) load_b(g_whi, (nc + 1) * 128, Bs, tid, NTHREADS);

        // epilogue -> g_qkv (fp32, +bias)
        {
            float* base = g_qkv + (size_t)(tok0 + a_row) * NQKV
                        + nc * 128 + warp_n * 32 + ac;
            const float* bb = s_bias + nc * 128 + warp_n * 32 + ac;
            #pragma unroll
            for (int m = 0; m < 4; m++) {
                #pragma unroll
                for (int j = 0; j < 4; j++) {
                    float b0 = bb[j * 8], b1 = bb[j * 8 + 1];
                    float* p = base + (size_t)m * 16 * NQKV + j * 8;
                    *(float2*)p = make_float2(c[m][j][0] + b0, c[m][j][1] + b1);
                    *(float2*)(p + (size_t)8 * NQKV) =
                        make_float2(c[m][j][2] + b0, c[m][j][3] + b1);
                }
            }
        }
        __syncthreads();
    }

    // ---- Phase C: attention (fp32), writes o split directly into Ah/Al
    {
        const float SCALE = 0.08838834764831845f;  // 128^-0.5
        #pragma unroll 1
        for (int pp = 0; pp < 8; pp++) {
            const int p = wid + pp * 8;            // 0..63 (group,head) pairs
            const int g = p >> 1, h = p & 1;
            const float* qb = g_qkv + (size_t)(tok0 + g * 4) * NQKV + h * 128;
            const float* kb = qb + 256;
            const float* vb = qb + 512;

            const int pid = lane >> 1, si = pid >> 2, sj = pid & 3, half = lane & 1;
            const float4* q4 = (const float4*)(qb + si * NQKV + half * 64);
            const float4* k4 = (const float4*)(kb + sj * NQKV + half * 64);
            float partial = 0.f;
            #pragma unroll
            for (int d = 0; d < 16; d++) {
                float4 a = __ldg(q4 + d), b = __ldg(k4 + d);
                partial += a.x * b.x + a.y * b.y + a.z * b.z + a.w * b.w;
            }
            partial += __shfl_xor_sync(0xffffffffu, partial, 1);
            const float sc = partial * SCALE;
            float mx = sc;
            mx = fmaxf(mx, __shfl_xor_sync(0xffffffffu, mx, 2));
            mx = fmaxf(mx, __shfl_xor_sync(0xffffffffu, mx, 4));
            float e = __expf(sc - mx);
            float ssum = e;
            ssum += __shfl_xor_sync(0xffffffffu, ssum, 2);
            ssum += __shfl_xor_sync(0xffffffffu, ssum, 4);
            const float P = e / ssum;
            if (half == 0) s_red[wid * 16 + pid] = P;
            __syncwarp();

            const int d0 = lane * 4;
            float4 vv[4];
            #pragma unroll
            for (int j2 = 0; j2 < 4; j2++)
                vv[j2] = __ldg((const float4*)(vb + j2 * NQKV + d0));
            #pragma unroll
            for (int i2 = 0; i2 < 4; i2++) {
                float4 o4 = make_float4(0.f, 0.f, 0.f, 0.f);
                #pragma unroll
                for (int j2 = 0; j2 < 4; j2++) {
                    const float pij = s_red[wid * 16 + i2 * 4 + j2];
                    o4.x += pij * vv[j2].x; o4.y += pij * vv[j2].y;
                    o4.z += pij * vv[j2].z; o4.w += pij * vv[j2].w;
                }
                uint32_t h0, h1, l0, l1;
                SPLIT4(o4.x, o4.y, o4.z, o4.w, h0, h1, l0, l1);
                const int off = (g * 4 + i2) * SA + h * 128 + d0;
                *(uint2*)(Ah + off) = make_uint2(h0, h1);
                *(uint2*)(Al + off) = make_uint2(l0, l1);
            }
            __syncwarp();
        }
    }
    __syncthreads();

    // ---- Phase E: out projection, 2 N-chunks, +bias +residual
    load_b(g_whi, NQKV, Bs, tid, NTHREADS);
    __syncthreads();
    for (int nc = 0; nc < 2; nc++) {
        float c[4][4][4];
        #pragma unroll
        for (int m = 0; m < 4; m++)
            #pragma unroll
            for (int j = 0; j < 4; j++)
                #pragma unroll
                for (int q = 0; q < 4; q++) c[m][j][q] = 0.f;

        gemm_accum(Ah, Bs, c, a_row, b_row, ac);
        gemm_accum(Al, Bs, c, a_row, b_row, ac);
        __syncthreads();
        load_b(g_wlo, NQKV + nc * 128, Bs, tid, NTHREADS);
        __syncthreads();
        gemm_accum(Ah, Bs, c, a_row, b_row, ac);
        __syncthreads();
        if (nc == 0) load_b(g_whi, NQKV + 128, Bs, tid, NTHREADS);

        {
            const int col0 = nc * 128 + warp_n * 32 + ac;
            const float* bb = s_bias + NQKV + col0;
            #pragma unroll
            for (int m = 0; m < 4; m++) {
                const int row = tok0 + a_row + m * 16;
                #pragma unroll
                for (int j = 0; j < 4; j++) {
                    float b0 = bb[j * 8], b1 = bb[j * 8 + 1];
                    size_t gi = (size_t)row * CDIM + col0 + j * 8;
                    float2 x0 = __ldg((const float2*)(x + gi));
                    float2 x1 = __ldg((const float2*)(x + gi + (size_t)8 * CDIM));
                    *(float2*)(out + gi) =
                        make_float2(c[m][j][0] + b0 + x0.x, c[m][j][1] + b1 + x0.y);
                    *(float2*)(out + gi + (size_t)8 * CDIM) =
                        make_float2(c[m][j][2] + b0 + x1.x, c[m][j][3] + b1 + x1.y);
                }
            }
        }
        __syncthreads();
    }
}

// ---------------------------------------------------------------------------
extern "C" void kernel_launch(void* const* d_in, const int* in_sizes, int n_in,
                              void* d_out, int out_size)
{
    const float* x     = (const float*)d_in[0];
    const float* qkv_w = (const float*)d_in[1];
    const float* qkv_b = (const float*)d_in[2];
    const float* out_w = (const float*)d_in[3];
    const float* out_b = (const float*)d_in[4];
    const float* ln_g  = (const float*)d_in[5];
    const float* ln_b  = (const float*)d_in[6];
    float* out = (float*)d_out;

    const int ntok = in_sizes[0] / CDIM;     // 131072
    const int nblk = ntok / MTILE;           // 1024

    ga_prep_w<<<(NQKV + CDIM) * CDIM / 256, 256>>>(qkv_w, out_w);

    cudaFuncSetAttribute(ga_main,
                         cudaFuncAttributeMaxDynamicSharedMemorySize, SMEM_BYTES);
    ga_main<<<nblk, NTHREADS, SMEM_BYTES>>>(x, qkv_b, out_b, ln_g, ln_b, out);
}